// round 14
// baseline (speedup 1.0000x reference)
#include <cuda_runtime.h>

// x_seq (T=16, N=8, C=64, H=64, W=64) fp32; conv_weight (64,64,3,3) fp32.
// z = conv3x3(pad=1) via Winograd F(2x2,3x3), then LIF scan over T.
#define T_  16
#define NB  8
#define C_  64
#define H_  64
#define W_  64
#define B_  (T_ * NB)
#define HW_ (H_ * W_)
#define CHW (C_ * HW_)
#define INNER (NB * CHW)        // 2097152 per timestep

// Scratch (static device globals — no allocation).
__device__ float g_z[(size_t)B_ * CHW];
__device__ float g_U[16 * 64 * 64];     // transformed weights U[pos][ci][co]

typedef unsigned long long u64;

__device__ __forceinline__ void fma2(u64& a, u64 x, u64 w) {
    asm("fma.rn.f32x2 %0, %1, %2, %3;" : "=l"(a) : "l"(x), "l"(w), "l"(a));
}
__device__ __forceinline__ u64 dup2(float v) {
    u64 r; asm("mov.b64 %0, {%1, %1};" : "=l"(r) : "f"(v)); return r;
}

__device__ __forceinline__ void cpa4(unsigned saddr, const float* g) {
    asm volatile("cp.async.ca.shared.global [%0], [%1], 4;"
                 :: "r"(saddr), "l"(g) : "memory");
}
__device__ __forceinline__ void cpa16(unsigned saddr, const float* g) {
    asm volatile("cp.async.ca.shared.global [%0], [%1], 16;"
                 :: "r"(saddr), "l"(g) : "memory");
}
#define CP_COMMIT() asm volatile("cp.async.commit_group;" ::: "memory")
#define CP_WAIT0()  asm volatile("cp.async.wait_group 0;" ::: "memory")

// ---------------------------------------------------------------------------
// Weight transform: U = G g G^T per (co, ci). Exact power-of-two coeffs.
// Layout g_U[pos][ci][co], pos = 4*i + j.
// ---------------------------------------------------------------------------
__global__ void wtrans_kernel(const float* __restrict__ w) {
    int idx = blockIdx.x * 256 + threadIdx.x;   // 0..4095
    int co = idx >> 6, ci = idx & 63;
    const float* g = w + ((size_t)co * 64 + ci) * 9;
    float g0[3] = {g[0], g[1], g[2]};
    float g1[3] = {g[3], g[4], g[5]};
    float g2[3] = {g[6], g[7], g[8]};
    float t[4][3];
#pragma unroll
    for (int j = 0; j < 3; j++) {
        t[0][j] = g0[j];
        t[1][j] = 0.5f * (g0[j] + g1[j] + g2[j]);
        t[2][j] = 0.5f * (g0[j] - g1[j] + g2[j]);
        t[3][j] = g2[j];
    }
#pragma unroll
    for (int i = 0; i < 4; i++) {
        float u0 = t[i][0];
        float u1 = 0.5f * (t[i][0] + t[i][1] + t[i][2]);
        float u2 = 0.5f * (t[i][0] - t[i][1] + t[i][2]);
        float u3 = t[i][2];
        g_U[(4 * i + 0) * 4096 + ci * 64 + co] = u0;
        g_U[(4 * i + 1) * 4096 + ci * 64 + co] = u1;
        g_U[(4 * i + 2) * 4096 + ci * 64 + co] = u2;
        g_U[(4 * i + 3) * 4096 + ci * 64 + co] = u3;
    }
}

// ---------------------------------------------------------------------------
// Winograd F(2x2,3x3) conv, v3: single-level accumulators (m[16] only — no
// tot[] second level) to eliminate register spills, occupancy 3.
// Block = image x 8x8 output region (16 wtiles) x 32 couts; 8 cp.async
// double-buffered chunks of 8 cin. Per chunk: V = B^T d B into single-
// buffered VS, then 16 pos-GEMMs: thread=(pos,wtile), 128 FFMA2/chunk.
// smem (floats): XIN [0,1600) 2-buf | VS [1600,3776) 1-buf, pos stride 136 |
// UW [3776,11968) 2-buf. Exchange overlays from 1600 after the main loop.
// 47872 B static, 3 blocks/SM (143.6KB < 228KB), reg cap 85.
// ---------------------------------------------------------------------------
#define NCHUNK   8
#define CIN_CH   8
#define XCIW     100            // 10x10 input patch per ci
#define XINSZ    (CIN_CH * XCIW)    // 800 per buffer
#define VPOS_STR 136            // VS pos stride (padded)
#define XIN_OFF  0
#define VS_OFF   1600
#define UW_OFF   3776
#define EX_OFF   1600
#define SMF      11968

__global__ __launch_bounds__(256, 3)
void wino_kernel(const float* __restrict__ x) {
    __shared__ __align__(16) float sm[SMF];

    const int gy = blockIdx.x >> 3, gx = blockIdx.x & 7;   // 8x8 region grid
    const int b  = blockIdx.y;                              // image
    const int cog = blockIdx.z;                             // co group (32)
    const int R0 = gy * 8, C0 = gx * 8;
    const int tid = threadIdx.x;

    // ---- staging precompute: input slots (800 = 8ci x 10r x 10c) ----
    int xrel[4];
    unsigned vmask = 0;
#pragma unroll
    for (int s = 0; s < 4; s++) {
        int idx = tid + 256 * s;
        int ci = idx / XCIW;
        int rem = idx - ci * XCIW;
        int r = rem / 10, c = rem - r * 10;
        int gh = R0 - 1 + r, gw = C0 - 1 + c;
        bool valid = (idx < XINSZ) &&
                     ((unsigned)gh < (unsigned)H_) &&
                     ((unsigned)gw < (unsigned)W_);
        xrel[s] = ci * HW_ + gh * W_ + gw;
        if (valid) vmask |= (1u << s);
    }
    const float* xb = x + (size_t)b * CHW;
    const unsigned smb = (unsigned)__cvta_generic_to_shared(sm);

    // ---- zero both xin buffers (halo slots never rewritten) ----
    for (int i = tid; i < 2 * XINSZ; i += 256) sm[XIN_OFF + i] = 0.0f;
    __syncthreads();

    // ---- prefetch chunk 0 (input + transformed weights) ----
    {
#pragma unroll
        for (int s = 0; s < 4; s++)
            if (vmask & (1u << s))
                cpa4(smb + (unsigned)(XIN_OFF + tid + 256 * s) * 4u, xb + xrel[s]);
#pragma unroll
        for (int s = 0; s < 4; s++) {
            int g = tid + 256 * s;                 // 0..1023 vec4 groups
            int pos = g >> 6, r = g & 63;
            int ci_l = r >> 3, co4 = r & 7;
            const float* gp = &g_U[pos * 4096 + ci_l * 64 + cog * 32 + co4 * 4];
            cpa16(smb + (unsigned)(UW_OFF + g * 4) * 4u, gp);
        }
        CP_COMMIT();
    }

    u64 m[16];
#pragma unroll
    for (int j = 0; j < 16; j++) m[j] = 0ULL;

#pragma unroll 1
    for (int ch = 0; ch < NCHUNK; ch++) {
        const int buf = ch & 1;
        CP_WAIT0();
        __syncthreads();   // also orders prior GEMM before VS overwrite below

        // ---- V = B^T d B : 512 units (ci, i-row, wtile), 2 per thread ----
#pragma unroll
        for (int uu = 0; uu < 2; uu++) {
            int u  = tid + 256 * uu;
            int ci = u >> 6;              // 0..7
            int i  = (u >> 4) & 3;        // transform row 0..3
            int wt = u & 15;
            int wy = wt >> 2, wx = wt & 3;
            int rA = (i == 3) ? 1 : i;
            int rB = (i <= 1) ? 2 : ((i == 2) ? 1 : 3);
            float sgn = (i == 1) ? 1.0f : -1.0f;
            const float* dbase = &sm[XIN_OFF + buf * XINSZ + ci * XCIW +
                                     (2 * wy) * 10 + 2 * wx];
            float t0 = __fmaf_rn(sgn, dbase[rB * 10 + 0], dbase[rA * 10 + 0]);
            float t1 = __fmaf_rn(sgn, dbase[rB * 10 + 1], dbase[rA * 10 + 1]);
            float t2 = __fmaf_rn(sgn, dbase[rB * 10 + 2], dbase[rA * 10 + 2]);
            float t3 = __fmaf_rn(sgn, dbase[rB * 10 + 3], dbase[rA * 10 + 3]);
            float* vs = &sm[VS_OFF + ci * 16 + wt];
            vs[(4 * i + 0) * VPOS_STR] = t0 - t2;
            vs[(4 * i + 1) * VPOS_STR] = t1 + t2;
            vs[(4 * i + 2) * VPOS_STR] = t2 - t1;
            vs[(4 * i + 3) * VPOS_STR] = t1 - t3;
        }
        __syncthreads();

        // ---- prefetch next chunk into other buffers ----
        if (ch < NCHUNK - 1) {
            const float* xp = xb + (ch + 1) * CIN_CH * HW_;
            const int nb = buf ^ 1;
#pragma unroll
            for (int s = 0; s < 4; s++)
                if (vmask & (1u << s))
                    cpa4(smb + (unsigned)(XIN_OFF + nb * XINSZ + tid + 256 * s) * 4u,
                         xp + xrel[s]);
#pragma unroll
            for (int s = 0; s < 4; s++) {
                int g = tid + 256 * s;
                int pos = g >> 6, r = g & 63;
                int ci_l = r >> 3, co4 = r & 7;
                const float* gp = &g_U[pos * 4096 + ((ch + 1) * CIN_CH + ci_l) * 64 +
                                       cog * 32 + co4 * 4];
                cpa16(smb + (unsigned)(UW_OFF + nb * 4096 + g * 4) * 4u, gp);
            }
            CP_COMMIT();
        }

        // ---- pos-GEMM: thread = (pos, wtile); m[32 co] += U * V over 8 ci ----
        {
            int pos = tid >> 4, wt = tid & 15;
#pragma unroll
            for (int ci = 0; ci < CIN_CH; ci++) {
                u64 v = dup2(sm[VS_OFF + pos * VPOS_STR + ci * 16 + wt]);
                const ulonglong2* uq = (const ulonglong2*)
                    &sm[UW_OFF + buf * 4096 + pos * 256 + ci * 32];
#pragma unroll
                for (int q = 0; q < 8; q++) {
                    ulonglong2 u = uq[q];
                    fma2(m[2 * q + 0], v, u.x);
                    fma2(m[2 * q + 1], v, u.y);
                }
            }
        }
    }
    __syncthreads();

    // ---- exchange + output transform (2 co-chunks of 16) ----
    const int wy = tid >> 6, co_l = (tid >> 2) & 15, wx = tid & 3;
    const int pos_w = tid >> 4, wt_w = tid & 15;
#pragma unroll 1
    for (int c = 0; c < 2; c++) {
#pragma unroll
        for (int j2 = 0; j2 < 8; j2++) {
            *reinterpret_cast<u64*>(
                &sm[EX_OFF + wt_w * 290 + pos_w * 18 + 2 * j2]) = m[8 * c + j2];
        }
        __syncthreads();
        float mm[16];
        {
            int base = EX_OFF + (wy * 4 + wx) * 290 + co_l;
#pragma unroll
            for (int p = 0; p < 16; p++) mm[p] = sm[base + p * 18];
        }
        float t0[4], t1[4];
#pragma unroll
        for (int j = 0; j < 4; j++) {
            t0[j] = mm[0 + j] + mm[4 + j] + mm[8 + j];
            t1[j] = mm[4 + j] - mm[8 + j] - mm[12 + j];
        }
        float o00 = t0[0] + t0[1] + t0[2];
        float o01 = t0[1] - t0[2] - t0[3];
        float o10 = t1[0] + t1[1] + t1[2];
        float o11 = t1[1] - t1[2] - t1[3];
        int co_g = cog * 32 + c * 16 + co_l;
        size_t ob = (size_t)b * CHW + (size_t)co_g * HW_ +
                    (size_t)(R0 + 2 * wy) * W_ + (C0 + 2 * wx);
        *(float2*)&g_z[ob]       = make_float2(o00, o01);
        *(float2*)&g_z[ob + W_]  = make_float2(o10, o11);
        __syncthreads();
    }
}

// ---------------------------------------------------------------------------
// LIF scan over T, float4-vectorized: v += (x - v)/2 ; spike=(v>=1); reset 0.
// ---------------------------------------------------------------------------
__global__ __launch_bounds__(256)
void lif_kernel(float* __restrict__ out) {
    int i = blockIdx.x * blockDim.x + threadIdx.x;   // float4 index
    const float4* z4 = (const float4*)g_z;
    float4* o4 = (float4*)out;
    float4 v = make_float4(0.f, 0.f, 0.f, 0.f);
#pragma unroll
    for (int t = 0; t < T_; t++) {
        float4 xv = z4[(size_t)t * (INNER / 4) + i];
        v.x = v.x + (xv.x - v.x) * 0.5f;
        v.y = v.y + (xv.y - v.y) * 0.5f;
        v.z = v.z + (xv.z - v.z) * 0.5f;
        v.w = v.w + (xv.w - v.w) * 0.5f;
        float4 s;
        s.x = (v.x >= 1.0f) ? 1.0f : 0.0f;
        s.y = (v.y >= 1.0f) ? 1.0f : 0.0f;
        s.z = (v.z >= 1.0f) ? 1.0f : 0.0f;
        s.w = (v.w >= 1.0f) ? 1.0f : 0.0f;
        o4[(size_t)t * (INNER / 4) + i] = s;
        if (v.x >= 1.0f) v.x = 0.0f;
        if (v.y >= 1.0f) v.y = 0.0f;
        if (v.z >= 1.0f) v.z = 0.0f;
        if (v.w >= 1.0f) v.w = 0.0f;
    }
}

extern "C" void kernel_launch(void* const* d_in, const int* in_sizes, int n_in,
                              void* d_out, int out_size) {
    const float* x = (const float*)d_in[0];
    const float* w = (const float*)d_in[1];
    float* out = (float*)d_out;

    wtrans_kernel<<<16, 256>>>(w);                       // U = G g G^T
    dim3 grid(64, B_, 2);                                // 8x8 regions, 128 imgs, 2 co groups
    wino_kernel<<<grid, 256>>>(x);
    lif_kernel<<<(INNER / 4) / 256, 256>>>(out);
}

// round 15
// speedup vs baseline: 1.4632x; 1.4632x over previous
#include <cuda_runtime.h>

// x_seq (T=16, N=8, C=64, H=64, W=64) fp32; conv_weight (64,64,3,3) fp32.
// z = conv3x3(pad=1) over B=T*N=128 images, then LIF scan over T.
#define T_  16
#define NB  8
#define C_  64
#define H_  64
#define W_  64
#define B_  (T_ * NB)
#define HW_ (H_ * W_)
#define CHW (C_ * HW_)
#define INNER (NB * CHW)        // 2097152 per timestep

#define TS_H 16
#define TS_W 32                 // tile 32 wide; 2 adjacent pixels per thread
#define CIN_CHUNK 4
#define NCHUNK (C_ / CIN_CHUNK) // 16
#define COUT_PER  16            // 4 cout groups
#define XROW 35                 // 32 + 2 halo, padded odd (bank-free strided loads)
#define XCI  (18 * XROW)        // 630 floats per ci slice
#define XELEMS (CIN_CHUNK * XCI)          // 2520 per buffer
#define WELEMS (CIN_CHUNK * 9 * COUT_PER) // 576 per buffer
#define XSLOTS 10               // ceil(2520/256)

// Conv output scratch (static device global — no allocation).
__device__ float g_z[(size_t)B_ * CHW];

typedef unsigned long long u64;

// Packed fp32x2 ops (lane-wise rn-rounded fp32).
__device__ __forceinline__ void fma2(u64& a, u64 x, u64 w) {
    asm("fma.rn.f32x2 %0, %1, %2, %3;" : "=l"(a) : "l"(x), "l"(w), "l"(a));
}
__device__ __forceinline__ void add2(u64& a, u64 b) {
    asm("add.rn.f32x2 %0, %1, %2;" : "=l"(a) : "l"(a), "l"(b));
}
__device__ __forceinline__ u64 dup2(float v) {
    u64 r; asm("mov.b64 %0, {%1, %1};" : "=l"(r) : "f"(v)); return r;
}
__device__ __forceinline__ void unpk(u64 v, float& lo, float& hi) {
    asm("mov.b64 {%0, %1}, %2;" : "=f"(lo), "=f"(hi) : "l"(v));
}

__device__ __forceinline__ void cpa4(unsigned saddr, const float* g) {
    asm volatile("cp.async.ca.shared.global [%0], [%1], 4;"
                 :: "r"(saddr), "l"(g) : "memory");
}
#define CP_COMMIT() asm volatile("cp.async.commit_group;" ::: "memory")
#define CP_WAIT1()  asm volatile("cp.async.wait_group 1;" ::: "memory")

// ---------------------------------------------------------------------------
// Direct 3x3 conv, cp.async TRIPLE-buffered, packed-cout FFMA2.
// One block = 1 image x 32x16 tile x 16 couts; each thread computes 2
// horizontally-adjacent pixels. Accumulator lanes pack (co, co+1): weight
// pairs come straight out of smem as u64 halves of broadcast LDS.128;
// input taps splatted (x,x) once per column. Inner loop identical to the
// proven 903us kernel; triple buffering cuts sync to 1 BAR + 1 wait per
// chunk (prefetch for ch+2 lands in the buffer consumed at ch-1, whose
// reads are ordered by the iter-ch barrier) and doubles prefetch distance.
// ---------------------------------------------------------------------------
__global__ __launch_bounds__(256, 2)
void conv3x3_kernel(const float* __restrict__ x, const float* __restrict__ w) {
    __shared__ __align__(16) float xs[3][XELEMS];   // 3 x 10080 B
    __shared__ __align__(16) float ws[3][WELEMS];   // 3 x  2304 B

    const int tile = blockIdx.x;          // 0..7 : 2 across x 4 down
    const int b    = blockIdx.y;          // 0..127
    const int cg   = blockIdx.z;          // 0..3 cout group
    const int h0 = (tile >> 1) * TS_H;
    const int w0 = (tile & 1) * TS_W;
    const int tid = threadIdx.x;
    const int p  = tid & 15;              // pixel pair covers columns 2p, 2p+1
    const int py = tid >> 4;              // row 0..15

    // ---- precompute staging slots (fixed per thread for all chunks) ----
    int xrel[XSLOTS];
    unsigned vmask = 0;
#pragma unroll
    for (int s = 0; s < XSLOTS; s++) {
        int idx = tid + 256 * s;
        int ci  = idx / XCI;
        int rem = idx - ci * XCI;
        int r = rem / XROW, c = rem - r * XROW;
        int gh = h0 + r - 1, gw = w0 + c - 1;
        bool valid = (idx < XELEMS) && (c < 34) &&
                     ((unsigned)gh < (unsigned)H_) &&
                     ((unsigned)gw < (unsigned)W_);
        xrel[s] = ci * HW_ + gh * W_ + gw;
        if (valid) vmask |= (1u << s);
    }
    int wrel[3];
#pragma unroll
    for (int s = 0; s < 3; s++) {
        int idx = (tid + 256 * s) % WELEMS;
        int ci  = idx / (9 * COUT_PER);
        int rem = idx - ci * (9 * COUT_PER);
        int k  = rem >> 4;
        int co = rem & 15;
        wrel[s] = (cg * COUT_PER + co) * (C_ * 9) + ci * 9 + k;
    }
    const bool w2v = (tid < WELEMS - 512);

    const unsigned xsb = (unsigned)__cvta_generic_to_shared(&xs[0][0]);
    const unsigned wsb = (unsigned)__cvta_generic_to_shared(&ws[0][0]);
    const float* xbase = x + (size_t)b * CHW;

    // ---- zero all three xs buffers once (halo slots never rewritten) ----
    for (int i = tid; i < 3 * XELEMS; i += 256) (&xs[0][0])[i] = 0.0f;
    __syncthreads();

    // ---- prefetch chunks 0 and 1 ----
#pragma unroll
    for (int pc = 0; pc < 2; pc++) {
        const float* xp = xbase + pc * CIN_CHUNK * HW_;
        const float* wp = w + pc * CIN_CHUNK * 9;
        const unsigned xb = xsb + (unsigned)(pc * XELEMS) * 4u;
        const unsigned wb = wsb + (unsigned)(pc * WELEMS) * 4u;
#pragma unroll
        for (int s = 0; s < XSLOTS; s++)
            if (vmask & (1u << s))
                cpa4(xb + (unsigned)(tid + 256 * s) * 4u, xp + xrel[s]);
        cpa4(wb + (unsigned)tid * 4u, wp + wrel[0]);
        cpa4(wb + (unsigned)(tid + 256) * 4u, wp + wrel[1]);
        if (w2v) cpa4(wb + (unsigned)(tid + 512) * 4u, wp + wrel[2]);
        CP_COMMIT();
    }

    // Accumulators: lane pair = (co 2j, co 2j+1); tot0/a0 = pixel0, tot1/a1 = pixel1.
    u64 tot0[COUT_PER / 2], tot1[COUT_PER / 2];
#pragma unroll
    for (int j = 0; j < COUT_PER / 2; j++) { tot0[j] = 0ULL; tot1[j] = 0ULL; }

    int cur = 0, pf = 2;   // rolling buffer indices: compute buf, prefetch buf
#pragma unroll 1
    for (int ch = 0; ch < NCHUNK; ch++) {
        CP_WAIT1();        // group for chunk ch complete (<=1 group in flight)
        __syncthreads();   // all warps: ch data visible; ch-1 reads finished

        // ---- prefetch chunk ch+2 into buf pf (consumed at ch-1) ----
        if (ch + 2 < NCHUNK) {
            const float* xp = xbase + (ch + 2) * CIN_CHUNK * HW_;
            const float* wp = w + (ch + 2) * CIN_CHUNK * 9;
            const unsigned xb = xsb + (unsigned)(pf * XELEMS) * 4u;
            const unsigned wb = wsb + (unsigned)(pf * WELEMS) * 4u;
#pragma unroll
            for (int s = 0; s < XSLOTS; s++)
                if (vmask & (1u << s))
                    cpa4(xb + (unsigned)(tid + 256 * s) * 4u, xp + xrel[s]);
            cpa4(wb + (unsigned)tid * 4u, wp + wrel[0]);
            cpa4(wb + (unsigned)(tid + 256) * 4u, wp + wrel[1]);
            if (w2v) cpa4(wb + (unsigned)(tid + 512) * 4u, wp + wrel[2]);
        }
        CP_COMMIT();       // always commit (possibly empty) — uniform accounting

        // ---- compute chunk ch from buf cur (inner loop identical to 903us) ----
        u64 a0[COUT_PER / 2], a1[COUT_PER / 2];
#pragma unroll
        for (int j = 0; j < COUT_PER / 2; j++) { a0[j] = 0ULL; a1[j] = 0ULL; }

#pragma unroll
        for (int ci = 0; ci < CIN_CHUNK; ci++) {
            const float* xrow = &xs[cur][ci * XCI + py * XROW + 2 * p];
#pragma unroll
            for (int kh = 0; kh < 3; kh++) {
                u64 xd[4];
#pragma unroll
                for (int c = 0; c < 4; c++) xd[c] = dup2(xrow[kh * XROW + c]);
#pragma unroll
                for (int kw = 0; kw < 3; kw++) {
                    const u64 x0 = xd[kw];
                    const u64 x1 = xd[kw + 1];
                    const ulonglong2* wq = (const ulonglong2*)
                        &ws[cur][((ci * 3 + kh) * 3 + kw) * COUT_PER];
#pragma unroll
                    for (int q = 0; q < 4; q++) {     // 4 x LDS.128 broadcast
                        ulonglong2 wv = wq[q];
                        fma2(a0[q * 2 + 0], x0, wv.x);
                        fma2(a1[q * 2 + 0], x1, wv.x);
                        fma2(a0[q * 2 + 1], x0, wv.y);
                        fma2(a1[q * 2 + 1], x1, wv.y);
                    }
                }
            }
        }
        // fold 4-ci chunk into running totals (two-level, same order as 903us)
#pragma unroll
        for (int j = 0; j < COUT_PER / 2; j++) {
            add2(tot0[j], a0[j]);
            add2(tot1[j], a1[j]);
        }

        cur = (cur == 2) ? 0 : cur + 1;
        pf  = (pf  == 2) ? 0 : pf  + 1;
    }

    const int h = h0 + py, wcol = w0 + 2 * p;
    float* zb = &g_z[(size_t)b * CHW + (size_t)cg * COUT_PER * HW_ + h * W_ + wcol];
#pragma unroll
    for (int j = 0; j < COUT_PER / 2; j++) {
        float e0, e1, f0, f1;
        unpk(tot0[j], e0, e1);    // pixel0: co=2j, co=2j+1
        unpk(tot1[j], f0, f1);    // pixel1
        *(float2*)&zb[(size_t)(2 * j) * HW_]     = make_float2(e0, f0);
        *(float2*)&zb[(size_t)(2 * j + 1) * HW_] = make_float2(e1, f1);
    }
}

// ---------------------------------------------------------------------------
// LIF scan over T, float4-vectorized: v += (x - v)/2 ; spike=(v>=1); reset 0.
// ---------------------------------------------------------------------------
__global__ __launch_bounds__(256)
void lif_kernel(float* __restrict__ out) {
    int i = blockIdx.x * blockDim.x + threadIdx.x;   // float4 index
    const float4* z4 = (const float4*)g_z;
    float4* o4 = (float4*)out;
    float4 v = make_float4(0.f, 0.f, 0.f, 0.f);
#pragma unroll
    for (int t = 0; t < T_; t++) {
        float4 xv = z4[(size_t)t * (INNER / 4) + i];
        v.x = v.x + (xv.x - v.x) * 0.5f;
        v.y = v.y + (xv.y - v.y) * 0.5f;
        v.z = v.z + (xv.z - v.z) * 0.5f;
        v.w = v.w + (xv.w - v.w) * 0.5f;
        float4 s;
        s.x = (v.x >= 1.0f) ? 1.0f : 0.0f;
        s.y = (v.y >= 1.0f) ? 1.0f : 0.0f;
        s.z = (v.z >= 1.0f) ? 1.0f : 0.0f;
        s.w = (v.w >= 1.0f) ? 1.0f : 0.0f;
        o4[(size_t)t * (INNER / 4) + i] = s;
        if (v.x >= 1.0f) v.x = 0.0f;
        if (v.y >= 1.0f) v.y = 0.0f;
        if (v.z >= 1.0f) v.z = 0.0f;
        if (v.w >= 1.0f) v.w = 0.0f;
    }
}

extern "C" void kernel_launch(void* const* d_in, const int* in_sizes, int n_in,
                              void* d_out, int out_size) {
    const float* x = (const float*)d_in[0];
    const float* w = (const float*)d_in[1];
    float* out = (float*)d_out;

    dim3 grid(8, B_, 4);    // 2x4 tiles, 128 images, 4 cout groups
    conv3x3_kernel<<<grid, 256>>>(x, w);
    lif_kernel<<<(INNER / 4) / 256, 256>>>(out);
}

// round 16
// speedup vs baseline: 1.4641x; 1.0006x over previous
#include <cuda_runtime.h>

// x_seq (T=16, N=8, C=64, H=64, W=64) fp32; conv_weight (64,64,3,3) fp32.
// z = conv3x3(pad=1) over B=T*N=128 images, then LIF scan over T.
#define T_  16
#define NB  8
#define C_  64
#define H_  64
#define W_  64
#define B_  (T_ * NB)
#define HW_ (H_ * W_)
#define CHW (C_ * HW_)
#define INNER (NB * CHW)        // 2097152 per timestep

#define TS_H 16
#define TS_W 32                 // tile 32 wide; 2 adjacent pixels per thread
#define CIN_CHUNK 4
#define NCHUNK (C_ / CIN_CHUNK) // 16
#define COUT_PER  16            // 4 cout groups
#define XROW 35                 // 32 + 2 halo, padded odd (bank-free strided loads)
#define XCI  (18 * XROW)        // 630 floats per ci slice
#define XELEMS (CIN_CHUNK * XCI)          // 2520 per buffer
#define WELEMS (CIN_CHUNK * 9 * COUT_PER) // 576 per buffer
#define XSLOTS 10               // ceil(2520/256)

// Conv output scratch (static device global — no allocation).
__device__ float g_z[(size_t)B_ * CHW];

typedef unsigned long long u64;

// Packed fp32x2 ops (lane-wise rn-rounded fp32).
__device__ __forceinline__ void fma2(u64& a, u64 x, u64 w) {
    asm("fma.rn.f32x2 %0, %1, %2, %3;" : "=l"(a) : "l"(x), "l"(w), "l"(a));
}
__device__ __forceinline__ void add2(u64& a, u64 b) {
    asm("add.rn.f32x2 %0, %1, %2;" : "=l"(a) : "l"(a), "l"(b));
}
__device__ __forceinline__ u64 dup2(float v) {
    u64 r; asm("mov.b64 %0, {%1, %1};" : "=l"(r) : "f"(v)); return r;
}
__device__ __forceinline__ void unpk(u64 v, float& lo, float& hi) {
    asm("mov.b64 {%0, %1}, %2;" : "=f"(lo), "=f"(hi) : "l"(v));
}

__device__ __forceinline__ void cpa4(unsigned saddr, const float* g) {
    asm volatile("cp.async.ca.shared.global [%0], [%1], 4;"
                 :: "r"(saddr), "l"(g) : "memory");
}
#define CP_COMMIT() asm volatile("cp.async.commit_group;" ::: "memory")
#define CP_WAIT1()  asm volatile("cp.async.wait_group 1;" ::: "memory")

// ---------------------------------------------------------------------------
// Direct 3x3 conv, cp.async TRIPLE-buffered, packed-cout FFMA2.
// One block = 1 image x 32x16 tile x 16 couts; each thread computes 2
// horizontally-adjacent pixels. Accumulator lanes pack (co, co+1): weight
// pairs come straight out of smem as u64 halves of broadcast LDS.128;
// input taps splatted (x,x) once per column. Inner loop identical to the
// proven 903us kernel; triple buffering cuts sync to 1 BAR + 1 wait per
// chunk (prefetch for ch+2 lands in the buffer consumed at ch-1, whose
// reads are ordered by the iter-ch barrier) and doubles prefetch distance.
// ---------------------------------------------------------------------------
__global__ __launch_bounds__(256, 2)
void conv3x3_kernel(const float* __restrict__ x, const float* __restrict__ w) {
    __shared__ __align__(16) float xs[3][XELEMS];   // 3 x 10080 B
    __shared__ __align__(16) float ws[3][WELEMS];   // 3 x  2304 B

    const int tile = blockIdx.x;          // 0..7 : 2 across x 4 down
    const int b    = blockIdx.y;          // 0..127
    const int cg   = blockIdx.z;          // 0..3 cout group
    const int h0 = (tile >> 1) * TS_H;
    const int w0 = (tile & 1) * TS_W;
    const int tid = threadIdx.x;
    const int p  = tid & 15;              // pixel pair covers columns 2p, 2p+1
    const int py = tid >> 4;              // row 0..15

    // ---- precompute staging slots (fixed per thread for all chunks) ----
    int xrel[XSLOTS];
    unsigned vmask = 0;
#pragma unroll
    for (int s = 0; s < XSLOTS; s++) {
        int idx = tid + 256 * s;
        int ci  = idx / XCI;
        int rem = idx - ci * XCI;
        int r = rem / XROW, c = rem - r * XROW;
        int gh = h0 + r - 1, gw = w0 + c - 1;
        bool valid = (idx < XELEMS) && (c < 34) &&
                     ((unsigned)gh < (unsigned)H_) &&
                     ((unsigned)gw < (unsigned)W_);
        xrel[s] = ci * HW_ + gh * W_ + gw;
        if (valid) vmask |= (1u << s);
    }
    int wrel[3];
#pragma unroll
    for (int s = 0; s < 3; s++) {
        int idx = (tid + 256 * s) % WELEMS;
        int ci  = idx / (9 * COUT_PER);
        int rem = idx - ci * (9 * COUT_PER);
        int k  = rem >> 4;
        int co = rem & 15;
        wrel[s] = (cg * COUT_PER + co) * (C_ * 9) + ci * 9 + k;
    }
    const bool w2v = (tid < WELEMS - 512);

    const unsigned xsb = (unsigned)__cvta_generic_to_shared(&xs[0][0]);
    const unsigned wsb = (unsigned)__cvta_generic_to_shared(&ws[0][0]);
    const float* xbase = x + (size_t)b * CHW;

    // ---- zero all three xs buffers once (halo slots never rewritten) ----
    for (int i = tid; i < 3 * XELEMS; i += 256) (&xs[0][0])[i] = 0.0f;
    __syncthreads();

    // ---- prefetch chunks 0 and 1 ----
#pragma unroll
    for (int pc = 0; pc < 2; pc++) {
        const float* xp = xbase + pc * CIN_CHUNK * HW_;
        const float* wp = w + pc * CIN_CHUNK * 9;
        const unsigned xb = xsb + (unsigned)(pc * XELEMS) * 4u;
        const unsigned wb = wsb + (unsigned)(pc * WELEMS) * 4u;
#pragma unroll
        for (int s = 0; s < XSLOTS; s++)
            if (vmask & (1u << s))
                cpa4(xb + (unsigned)(tid + 256 * s) * 4u, xp + xrel[s]);
        cpa4(wb + (unsigned)tid * 4u, wp + wrel[0]);
        cpa4(wb + (unsigned)(tid + 256) * 4u, wp + wrel[1]);
        if (w2v) cpa4(wb + (unsigned)(tid + 512) * 4u, wp + wrel[2]);
        CP_COMMIT();
    }

    // Accumulators: lane pair = (co 2j, co 2j+1); tot0/a0 = pixel0, tot1/a1 = pixel1.
    u64 tot0[COUT_PER / 2], tot1[COUT_PER / 2];
#pragma unroll
    for (int j = 0; j < COUT_PER / 2; j++) { tot0[j] = 0ULL; tot1[j] = 0ULL; }

    int cur = 0, pf = 2;   // rolling buffer indices: compute buf, prefetch buf
#pragma unroll 1
    for (int ch = 0; ch < NCHUNK; ch++) {
        CP_WAIT1();        // group for chunk ch complete (<=1 group in flight)
        __syncthreads();   // all warps: ch data visible; ch-1 reads finished

        // ---- prefetch chunk ch+2 into buf pf (consumed at ch-1) ----
        if (ch + 2 < NCHUNK) {
            const float* xp = xbase + (ch + 2) * CIN_CHUNK * HW_;
            const float* wp = w + (ch + 2) * CIN_CHUNK * 9;
            const unsigned xb = xsb + (unsigned)(pf * XELEMS) * 4u;
            const unsigned wb = wsb + (unsigned)(pf * WELEMS) * 4u;
#pragma unroll
            for (int s = 0; s < XSLOTS; s++)
                if (vmask & (1u << s))
                    cpa4(xb + (unsigned)(tid + 256 * s) * 4u, xp + xrel[s]);
            cpa4(wb + (unsigned)tid * 4u, wp + wrel[0]);
            cpa4(wb + (unsigned)(tid + 256) * 4u, wp + wrel[1]);
            if (w2v) cpa4(wb + (unsigned)(tid + 512) * 4u, wp + wrel[2]);
        }
        CP_COMMIT();       // always commit (possibly empty) — uniform accounting

        // ---- compute chunk ch from buf cur (inner loop identical to 903us) ----
        u64 a0[COUT_PER / 2], a1[COUT_PER / 2];
#pragma unroll
        for (int j = 0; j < COUT_PER / 2; j++) { a0[j] = 0ULL; a1[j] = 0ULL; }

#pragma unroll
        for (int ci = 0; ci < CIN_CHUNK; ci++) {
            const float* xrow = &xs[cur][ci * XCI + py * XROW + 2 * p];
#pragma unroll
            for (int kh = 0; kh < 3; kh++) {
                u64 xd[4];
#pragma unroll
                for (int c = 0; c < 4; c++) xd[c] = dup2(xrow[kh * XROW + c]);
#pragma unroll
                for (int kw = 0; kw < 3; kw++) {
                    const u64 x0 = xd[kw];
                    const u64 x1 = xd[kw + 1];
                    const ulonglong2* wq = (const ulonglong2*)
                        &ws[cur][((ci * 3 + kh) * 3 + kw) * COUT_PER];
#pragma unroll
                    for (int q = 0; q < 4; q++) {     // 4 x LDS.128 broadcast
                        ulonglong2 wv = wq[q];
                        fma2(a0[q * 2 + 0], x0, wv.x);
                        fma2(a1[q * 2 + 0], x1, wv.x);
                        fma2(a0[q * 2 + 1], x0, wv.y);
                        fma2(a1[q * 2 + 1], x1, wv.y);
                    }
                }
            }
        }
        // fold 4-ci chunk into running totals (two-level, same order as 903us)
#pragma unroll
        for (int j = 0; j < COUT_PER / 2; j++) {
            add2(tot0[j], a0[j]);
            add2(tot1[j], a1[j]);
        }

        cur = (cur == 2) ? 0 : cur + 1;
        pf  = (pf  == 2) ? 0 : pf  + 1;
    }

    const int h = h0 + py, wcol = w0 + 2 * p;
    float* zb = &g_z[(size_t)b * CHW + (size_t)cg * COUT_PER * HW_ + h * W_ + wcol];
#pragma unroll
    for (int j = 0; j < COUT_PER / 2; j++) {
        float e0, e1, f0, f1;
        unpk(tot0[j], e0, e1);    // pixel0: co=2j, co=2j+1
        unpk(tot1[j], f0, f1);    // pixel1
        *(float2*)&zb[(size_t)(2 * j) * HW_]     = make_float2(e0, f0);
        *(float2*)&zb[(size_t)(2 * j + 1) * HW_] = make_float2(e1, f1);
    }
}

// ---------------------------------------------------------------------------
// LIF scan over T, float4-vectorized: v += (x - v)/2 ; spike=(v>=1); reset 0.
// ---------------------------------------------------------------------------
__global__ __launch_bounds__(256)
void lif_kernel(float* __restrict__ out) {
    int i = blockIdx.x * blockDim.x + threadIdx.x;   // float4 index
    const float4* z4 = (const float4*)g_z;
    float4* o4 = (float4*)out;
    float4 v = make_float4(0.f, 0.f, 0.f, 0.f);
#pragma unroll
    for (int t = 0; t < T_; t++) {
        float4 xv = z4[(size_t)t * (INNER / 4) + i];
        v.x = v.x + (xv.x - v.x) * 0.5f;
        v.y = v.y + (xv.y - v.y) * 0.5f;
        v.z = v.z + (xv.z - v.z) * 0.5f;
        v.w = v.w + (xv.w - v.w) * 0.5f;
        float4 s;
        s.x = (v.x >= 1.0f) ? 1.0f : 0.0f;
        s.y = (v.y >= 1.0f) ? 1.0f : 0.0f;
        s.z = (v.z >= 1.0f) ? 1.0f : 0.0f;
        s.w = (v.w >= 1.0f) ? 1.0f : 0.0f;
        o4[(size_t)t * (INNER / 4) + i] = s;
        if (v.x >= 1.0f) v.x = 0.0f;
        if (v.y >= 1.0f) v.y = 0.0f;
        if (v.z >= 1.0f) v.z = 0.0f;
        if (v.w >= 1.0f) v.w = 0.0f;
    }
}

extern "C" void kernel_launch(void* const* d_in, const int* in_sizes, int n_in,
                              void* d_out, int out_size) {
    const float* x = (const float*)d_in[0];
    const float* w = (const float*)d_in[1];
    float* out = (float*)d_out;

    dim3 grid(8, B_, 4);    // 2x4 tiles, 128 images, 4 cout groups
    conv3x3_kernel<<<grid, 256>>>(x, w);
    lif_kernel<<<(INNER / 4) / 256, 256>>>(out);
}